// round 14
// baseline (speedup 1.0000x reference)
#include <cuda_runtime.h>
#include <cuda_fp16.h>
#include <cstdint>

// ============================================================================
// R14 = R10 structure, but A removed from smem entirely: A fragments come from
// global LDG.64 (L1-cached) with warp-cooperative prefetch.global.L1 issued 2
// chunks ahead. Pipeline stages carry B only. B via ldmatrix (R10-proven).
// ============================================================================
#define KDIM      784
#define KPAD      800
#define KCH       32
#define NCHUNK    25
#define MT        128
#define NT        128
#define NSTAGES   3
#define THREADS   256         // 8 warps: 4 in M x 2 in N, warp tile M32xN64

#define B_BYTES   (NT * 80)                 // 10240 per stage (fp16, 80 B rows)
#define STAGE_F   (B_BYTES / 4)             // 2560 floats
#define PH        130

// smem float offsets
#define OF_PIPE   0                         // 3*2560 = 7680 floats (30720 B)
#define OF_H      7680                      // h[128][130] = 16640 floats
#define OF_W2     24320                     // 1280
#define OF_B1     25600                     // 128
#define OF_B2     25728                     // 16
#define SMEM_FLOATS 25744
#define SMEM_BYTES  (SMEM_FLOATS * 4)       // 102976 -> 2 CTAs/SM
// epilogue overlays the (dead) pipe region:
#define OF_PART   0                         // 2560
#define OF_OUTS   2560                      // 1280

__device__ __align__(16) __half g_Wt16[NT * KPAD];

// ============================================================================
// helpers (baseline PTX only)
// ============================================================================
__device__ __forceinline__ uint32_t smem_u32(const void* p) {
    uint32_t a;
    asm("{ .reg .u64 t; cvta.to.shared.u64 t, %1; cvt.u32.u64 %0, t; }" : "=r"(a) : "l"(p));
    return a;
}
__device__ __forceinline__ uint32_t pack_f16x2(float lo, float hi) {
    uint32_t r;
    asm("cvt.rn.f16x2.f32 %0, %2, %1;" : "=r"(r) : "f"(lo), "f"(hi));
    return r;
}
__device__ __forceinline__ void cp_async16(uint32_t dst_smem, const void* src) {
    asm volatile("cp.async.cg.shared.global [%0], [%1], 16;" :: "r"(dst_smem), "l"(src) : "memory");
}
__device__ __forceinline__ void cp_commit() { asm volatile("cp.async.commit_group;" ::: "memory"); }
__device__ __forceinline__ void cp_wait1()  { asm volatile("cp.async.wait_group 1;" ::: "memory"); }
__device__ __forceinline__ void cp_wait0()  { asm volatile("cp.async.wait_group 0;" ::: "memory"); }
__device__ __forceinline__ void prefetch_l1(const void* p) {
    asm volatile("prefetch.global.L1 [%0];" :: "l"(p));
}
__device__ __forceinline__ void ldmatrix_x4(uint32_t* r, uint32_t addr) {
    asm volatile("ldmatrix.sync.aligned.m8n8.x4.shared.b16 {%0,%1,%2,%3}, [%4];"
                 : "=r"(r[0]), "=r"(r[1]), "=r"(r[2]), "=r"(r[3]) : "r"(addr));
}
__device__ __forceinline__ void mma_f16(float* c, const uint32_t* a, uint32_t b0, uint32_t b1) {
    asm volatile("mma.sync.aligned.m16n8k16.row.col.f32.f16.f16.f32 "
                 "{%0,%1,%2,%3}, {%4,%5,%6,%7}, {%8,%9}, {%0,%1,%2,%3};"
                 : "+f"(c[0]), "+f"(c[1]), "+f"(c[2]), "+f"(c[3])
                 : "r"(a[0]), "r"(a[1]), "r"(a[2]), "r"(a[3]), "r"(b0), "r"(b1));
}

// ============================================================================
// Prep kernel: W_eff^T = (conv ⊗ w1), fp16-RN
// ============================================================================
__global__ void prep_kernel(const float* __restrict__ conv_w, const float* __restrict__ w1) {
    int idx = blockIdx.x * blockDim.x + threadIdx.x;
    if (idx >= NT * KPAD) return;
    int n = idx / KPAD;
    int k = idx - n * KPAD;
    float v = 0.f;
    if (k < KDIM) {
        int i = k / 28, j = k - (k / 28) * 28;
        #pragma unroll
        for (int dy = 0; dy < 3; ++dy) {
            int r = i - dy;
            if (r < 0 || r >= 26) continue;
            #pragma unroll
            for (int dx = 0; dx < 3; ++dx) {
                int c = j - dx;
                if (c < 0 || c >= 26) continue;
                v += conv_w[dy * 3 + dx] * w1[(r * 26 + c) * 128 + n];
            }
        }
    }
    g_Wt16[idx] = __float2half_rn(v);
}

// ============================================================================
// Main fused kernel: out = relu(x @ W_eff + b1) @ w2 + b2
// ============================================================================
__global__ void __launch_bounds__(THREADS, 2)
fused_mlp_kernel(const float* __restrict__ x, const float* __restrict__ b1,
                 const float* __restrict__ w2, const float* __restrict__ b2,
                 float* __restrict__ out, int Brows) {
    extern __shared__ float sm[];
    const int tid  = threadIdx.x;
    const int wid  = tid >> 5;
    const int lane = tid & 31;
    const int tg   = lane >> 2;          // 0..7
    const int tk   = lane & 3;           // 0..3
    const int mw   = (wid >> 1) * 32;    // 4 warps in M
    const int nw   = (wid & 1) * 64;     // 2 warps in N
    const int m0   = blockIdx.x * MT;

    for (int i = tid; i < 1280; i += THREADS) sm[OF_W2 + i] = w2[i];
    if (tid < 128) sm[OF_B1 + tid] = b1[tid];
    if (tid < 10)  sm[OF_B2 + tid] = b2[tid];

    const uint32_t pipe_sm = smem_u32(sm + OF_PIPE);

    // ---- B producer (2 cp.async / thread / chunk) ----
    auto issueB = [&](int c, int stage) {
        const uint32_t bbase = pipe_sm + (uint32_t)stage * B_BYTES;
        #pragma unroll
        for (int r = 0; r < 2; ++r) {
            const int j   = tid + r * THREADS;       // 0..511
            const int row = j >> 2, q = j & 3;       // row, 16B piece (8 halves)
            cp_async16(bbase + (uint32_t)(row * 80 + q * 16),
                       g_Wt16 + (size_t)row * KPAD + c * KCH + q * 8);
        }
    };

    // ---- A row pointers (per lane) + prefetch ----
    auto rowp = [&](int r) {
        int m = m0 + r; if (m >= Brows) m = Brows - 1;
        return x + (size_t)m * KDIM;
    };
    const float* xr0 = rowp(mw + tg);
    const float* xr1 = rowp(mw + tg + 8);
    const float* xr2 = rowp(mw + tg + 16);
    const float* xr3 = rowp(mw + tg + 24);

    // warp-cooperative A prefetch: lanes cover the warp's 32 M-rows; only the
    // nw==0 twin of each M-row-group issues (dedup). Two 64B-spaced hints per
    // row cover the 128B chunk span regardless of row alignment (rows are
    // 64B-aligned: 784*4 = 3136 B = 24.5 lines).
    auto prefA = [&](int c) {
        int m = m0 + mw + lane; if (m >= Brows) m = Brows - 1;
        int k0 = c * KCH; if (k0 + 16 > KDIM) k0 = KDIM - 32;   // clamp in-bounds
        const float* p = x + (size_t)m * KDIM + k0;
        prefetch_l1(p);
        prefetch_l1(p + 16);
    };

    float acc[2][8][4];
    #pragma unroll
    for (int mi = 0; mi < 2; ++mi)
        #pragma unroll
        for (int ni = 0; ni < 8; ++ni)
            #pragma unroll
            for (int e = 0; e < 4; ++e) acc[mi][ni][e] = 0.f;

    // B ldmatrix lane mapping (R9/R10-proven)
    const uint32_t b_lm = (uint32_t)(nw + (lane & 7) + ((lane & 16) >> 1)) * 80
                        + (uint32_t)((lane & 8) ? 16 : 0);

    // ---- prologue ----
    if ((wid & 1) == 0) { prefA(0); prefA(1); }
    issueB(0, 0); cp_commit();
    issueB(1, 1); cp_commit();

    // ---- mainloop ----
    int stage = 0;
    for (int c = 0; c < NCHUNK; ++c) {
        cp_wait1();
        __syncthreads();

        const int cn = c + NSTAGES - 1;
        int nstage = stage + 2; if (nstage >= NSTAGES) nstage -= NSTAGES;
        if (cn < NCHUNK) issueB(cn, nstage);
        cp_commit();
        if (c + 2 < NCHUNK && (wid & 1) == 0) prefA(c + 2);

        const uint32_t sb = pipe_sm + (uint32_t)stage * B_BYTES;
        const int kc = c * KCH;

        #pragma unroll
        for (int ks = 0; ks < KCH; ks += 16) {
            // A fragments straight from global (L1 hits after prefetch)
            uint32_t a[2][4];
            {
                const bool kv = (kc + ks) < KDIM;   // uniform: false only c==24,ks==16
                const int k0 = kc + ks + 2 * tk;
                float2 z = make_float2(0.f, 0.f);
                float2 v00 = kv ? *(const float2*)(xr0 + k0)     : z;
                float2 v01 = kv ? *(const float2*)(xr1 + k0)     : z;
                float2 v02 = kv ? *(const float2*)(xr0 + k0 + 8) : z;
                float2 v03 = kv ? *(const float2*)(xr1 + k0 + 8) : z;
                float2 v10 = kv ? *(const float2*)(xr2 + k0)     : z;
                float2 v11 = kv ? *(const float2*)(xr3 + k0)     : z;
                float2 v12 = kv ? *(const float2*)(xr2 + k0 + 8) : z;
                float2 v13 = kv ? *(const float2*)(xr3 + k0 + 8) : z;
                a[0][0] = pack_f16x2(v00.x, v00.y);
                a[0][1] = pack_f16x2(v01.x, v01.y);
                a[0][2] = pack_f16x2(v02.x, v02.y);
                a[0][3] = pack_f16x2(v03.x, v03.y);
                a[1][0] = pack_f16x2(v10.x, v10.y);
                a[1][1] = pack_f16x2(v11.x, v11.y);
                a[1][2] = pack_f16x2(v12.x, v12.y);
                a[1][3] = pack_f16x2(v13.x, v13.y);
            }
            // B fragments: ldmatrix.x4 from smem stage
            uint32_t b[8][2];
            #pragma unroll
            for (int g = 0; g < 4; ++g) {
                uint32_t r[4];
                ldmatrix_x4(r, sb + b_lm + (uint32_t)(g * 16 * 80 + ks * 2));
                b[2 * g][0]     = r[0]; b[2 * g][1]     = r[1];
                b[2 * g + 1][0] = r[2]; b[2 * g + 1][1] = r[3];
            }
            #pragma unroll
            for (int mi = 0; mi < 2; ++mi)
                #pragma unroll
                for (int ni = 0; ni < 8; ++ni)
                    mma_f16(acc[mi][ni], a[mi], b[ni][0], b[ni][1]);
        }
        ++stage; if (stage >= NSTAGES) stage = 0;
    }

    // ---- epilogue: h = relu(acc + b1) ----
    cp_wait0();
    __syncthreads();
    {
        float* h = sm + OF_H;   // [128][PH]
        #pragma unroll
        for (int mi = 0; mi < 2; ++mi) {
            #pragma unroll
            for (int ni = 0; ni < 8; ++ni) {
                const int r = mw + mi * 16 + tg;
                const int n = nw + ni * 8 + 2 * tk;
                const float bn0 = sm[OF_B1 + n], bn1 = sm[OF_B1 + n + 1];
                h[r * PH + n]           = fmaxf(acc[mi][ni][0] + bn0, 0.f);
                h[r * PH + n + 1]       = fmaxf(acc[mi][ni][1] + bn1, 0.f);
                h[(r + 8) * PH + n]     = fmaxf(acc[mi][ni][2] + bn0, 0.f);
                h[(r + 8) * PH + n + 1] = fmaxf(acc[mi][ni][3] + bn1, 0.f);
            }
        }
    }
    __syncthreads();

    // ---- GEMM2: split-K over 2 threads/row ----
    {
        const float* h = sm + OF_H;
        const int row  = tid & 127;
        const int half = tid >> 7;
        float o[10];
        #pragma unroll
        for (int n = 0; n < 10; ++n) o[n] = 0.f;
        #pragma unroll 8
        for (int k = half * 64; k < half * 64 + 64; ++k) {
            const float t = h[row * PH + k];
            const float* wr = sm + OF_W2 + k * 10;
            #pragma unroll
            for (int n = 0; n < 10; ++n) o[n] = fmaf(t, wr[n], o[n]);
        }
        #pragma unroll
        for (int n = 0; n < 10; ++n) sm[OF_PART + tid * 10 + n] = o[n];
    }
    __syncthreads();
    if (tid < 128) {
        #pragma unroll
        for (int n = 0; n < 10; ++n)
            sm[OF_OUTS + tid * 10 + n] = sm[OF_PART + tid * 10 + n]
                                       + sm[OF_PART + (tid + 128) * 10 + n]
                                       + sm[OF_B2 + n];
    }
    __syncthreads();

    // ---- coalesced store ----
    const int nvalid = (Brows - m0 < MT) ? (Brows - m0) : MT;
    if (nvalid == MT) {
        float4* dst = (float4*)(out + (size_t)m0 * 10);
        const float4* src = (const float4*)(sm + OF_OUTS);
        for (int i = tid; i < MT * 10 / 4; i += THREADS) dst[i] = src[i];
    } else {
        for (int i = tid; i < nvalid * 10; i += THREADS) out[(size_t)m0 * 10 + i] = sm[OF_OUTS + i];
    }
}

// ============================================================================
// Host launch
// ============================================================================
extern "C" void kernel_launch(void* const* d_in, const int* in_sizes, int n_in,
                              void* d_out, int out_size) {
    const float* x      = (const float*)d_in[0];
    const float* conv_w = (const float*)d_in[1];
    const float* w1     = (const float*)d_in[2];
    const float* b1     = (const float*)d_in[3];
    const float* w2     = (const float*)d_in[4];
    const float* b2     = (const float*)d_in[5];
    float* out          = (float*)d_out;
    const int Brows     = in_sizes[0] / KDIM;

    static int configured = 0;
    if (!configured) {
        cudaFuncSetAttribute(fused_mlp_kernel, cudaFuncAttributeMaxDynamicSharedMemorySize, SMEM_BYTES);
        configured = 1;
    }

    prep_kernel<<<(NT * KPAD + 255) / 256, 256>>>(conv_w, w1);

    const int grid = (Brows + MT - 1) / MT;
    fused_mlp_kernel<<<grid, THREADS, SMEM_BYTES>>>(x, b1, w2, b2, out, Brows);
}

// round 15
// speedup vs baseline: 1.3605x; 1.3605x over previous
#include <cuda_runtime.h>
#include <cuda_fp16.h>
#include <cstdint>

// ============================================================================
// R15 = R10 verbatim + per-warp ks-phase stagger: odd warps consume the ks=16
// half first, even warps ks=0 first. Breaks the post-barrier lockstep so the
// smem pipe (loads) and tensor pipe (MMAs) overlap instead of alternating.
// ============================================================================
#define KDIM      784
#define KPAD      800
#define KCH       32
#define NCHUNK    25
#define MT        128
#define NT        128
#define NSTAGES   3
#define THREADS   256         // 8 warps: 4 in M x 2 in N, warp tile M32xN64

#define APITCH    40                        // floats (160 B rows, conflict-free)
#define A_BYTES   (MT * APITCH * 4)         // 20480
#define B_BYTES   (NT * 80)                 // 10240 (fp16, 80 B rows)
#define STAGE_BYTES (A_BYTES + B_BYTES)     // 30720
#define STAGE_F   (STAGE_BYTES / 4)
#define PH        130

// smem float offsets (identical to R10)
#define OF_PIPE   0                         // 3*7680 = 23040 floats (92160 B)
#define OF_W2     23040
#define OF_B1     24320
#define OF_B2     24448
#define SMEM_FLOATS 24464
#define SMEM_BYTES  (SMEM_FLOATS * 4)       // 97856 -> 2 CTAs/SM
#define OF_PART   16640
#define OF_OUTS   19200

__device__ __align__(16) __half g_Wt16[NT * KPAD];

// ============================================================================
// helpers (baseline PTX only)
// ============================================================================
__device__ __forceinline__ uint32_t smem_u32(const void* p) {
    uint32_t a;
    asm("{ .reg .u64 t; cvta.to.shared.u64 t, %1; cvt.u32.u64 %0, t; }" : "=r"(a) : "l"(p));
    return a;
}
__device__ __forceinline__ uint32_t pack_f16x2(float lo, float hi) {
    uint32_t r;
    asm("cvt.rn.f16x2.f32 %0, %2, %1;" : "=r"(r) : "f"(lo), "f"(hi));
    return r;
}
__device__ __forceinline__ void cp_async16(uint32_t dst_smem, const void* src) {
    asm volatile("cp.async.cg.shared.global [%0], [%1], 16;" :: "r"(dst_smem), "l"(src) : "memory");
}
__device__ __forceinline__ void cp_async16_pred(uint32_t dst_smem, const void* src, int src_bytes) {
    asm volatile("cp.async.cg.shared.global [%0], [%1], 16, %2;"
                 :: "r"(dst_smem), "l"(src), "r"(src_bytes) : "memory");
}
__device__ __forceinline__ void cp_commit() { asm volatile("cp.async.commit_group;" ::: "memory"); }
__device__ __forceinline__ void cp_wait1()  { asm volatile("cp.async.wait_group 1;" ::: "memory"); }
__device__ __forceinline__ void cp_wait0()  { asm volatile("cp.async.wait_group 0;" ::: "memory"); }

__device__ __forceinline__ void ldmatrix_x4(uint32_t* r, uint32_t addr) {
    asm volatile("ldmatrix.sync.aligned.m8n8.x4.shared.b16 {%0,%1,%2,%3}, [%4];"
                 : "=r"(r[0]), "=r"(r[1]), "=r"(r[2]), "=r"(r[3]) : "r"(addr));
}
__device__ __forceinline__ void mma_f16(float* c, const uint32_t* a, uint32_t b0, uint32_t b1) {
    asm volatile("mma.sync.aligned.m16n8k16.row.col.f32.f16.f16.f32 "
                 "{%0,%1,%2,%3}, {%4,%5,%6,%7}, {%8,%9}, {%0,%1,%2,%3};"
                 : "+f"(c[0]), "+f"(c[1]), "+f"(c[2]), "+f"(c[3])
                 : "r"(a[0]), "r"(a[1]), "r"(a[2]), "r"(a[3]), "r"(b0), "r"(b1));
}

// ============================================================================
// Prep kernel: W_eff^T = (conv ⊗ w1), fp16-RN
// ============================================================================
__global__ void prep_kernel(const float* __restrict__ conv_w, const float* __restrict__ w1) {
    int idx = blockIdx.x * blockDim.x + threadIdx.x;
    if (idx >= NT * KPAD) return;
    int n = idx / KPAD;
    int k = idx - n * KPAD;
    float v = 0.f;
    if (k < KDIM) {
        int i = k / 28, j = k - (k / 28) * 28;
        #pragma unroll
        for (int dy = 0; dy < 3; ++dy) {
            int r = i - dy;
            if (r < 0 || r >= 26) continue;
            #pragma unroll
            for (int dx = 0; dx < 3; ++dx) {
                int c = j - dx;
                if (c < 0 || c >= 26) continue;
                v += conv_w[dy * 3 + dx] * w1[(r * 26 + c) * 128 + n];
            }
        }
    }
    g_Wt16[idx] = __float2half_rn(v);
}

// ============================================================================
// Main fused kernel: out = relu(x @ W_eff + b1) @ w2 + b2
// ============================================================================
__global__ void __launch_bounds__(THREADS, 2)
fused_mlp_kernel(const float* __restrict__ x, const float* __restrict__ b1,
                 const float* __restrict__ w2, const float* __restrict__ b2,
                 float* __restrict__ out, int Brows) {
    extern __shared__ float sm[];
    const int tid  = threadIdx.x;
    const int wid  = tid >> 5;
    const int lane = tid & 31;
    const int tg   = lane >> 2;          // 0..7
    const int tk   = lane & 3;           // 0..3
    const int mw   = (wid >> 1) * 32;    // 4 warps in M
    const int nw   = (wid & 1) * 64;     // 2 warps in N
    const int kphase = (wid & 1) * 16;   // per-warp ks-phase stagger
    const int m0   = blockIdx.x * MT;

    for (int i = tid; i < 1280; i += THREADS) sm[OF_W2 + i] = w2[i];
    if (tid < 128) sm[OF_B1 + tid] = b1[tid];
    if (tid < 10)  sm[OF_B2 + tid] = b2[tid];

    const uint32_t pipe_sm = smem_u32(sm + OF_PIPE);

    // ---- producer (R10-verbatim) ----
    auto issue = [&](int c, int stage) {
        const uint32_t sbase = pipe_sm + (uint32_t)stage * STAGE_BYTES;
        #pragma unroll
        for (int r = 0; r < 4; ++r) {
            const int j   = tid + r * THREADS;       // 0..1023
            const int row = j >> 3, q = j & 7;
            int msrc = m0 + row; if (msrc >= Brows) msrc = Brows - 1;
            const int k0 = c * KCH + q * 4;
            cp_async16_pred(sbase + (uint32_t)(row * APITCH + q * 4) * 4,
                            x + (size_t)msrc * KDIM + k0,
                            (k0 < KDIM) ? 16 : 0);
        }
        const uint32_t bbase = sbase + A_BYTES;
        #pragma unroll
        for (int r = 0; r < 2; ++r) {
            const int j   = tid + r * THREADS;       // 0..511
            const int row = j >> 2, q = j & 3;
            cp_async16(bbase + (uint32_t)(row * 80 + q * 16),
                       g_Wt16 + (size_t)row * KPAD + c * KCH + q * 8);
        }
    };

    float acc[2][8][4];
    #pragma unroll
    for (int mi = 0; mi < 2; ++mi)
        #pragma unroll
        for (int ni = 0; ni < 8; ++ni)
            #pragma unroll
            for (int e = 0; e < 4; ++e) acc[mi][ni][e] = 0.f;

    // B ldmatrix lane mapping (R9/R10-proven)
    const uint32_t b_lm = (uint32_t)A_BYTES
                        + (uint32_t)(nw + (lane & 7) + ((lane & 16) >> 1)) * 80
                        + (uint32_t)((lane & 8) ? 16 : 0);

    // ---- prologue: fill 2 stages ----
    issue(0, 0); cp_commit();
    issue(1, 1); cp_commit();

    // ---- mainloop (R10 structure; ks order staggered per warp) ----
    int stage = 0;
    for (int c = 0; c < NCHUNK; ++c) {
        cp_wait1();
        __syncthreads();

        const int cn = c + NSTAGES - 1;
        int nstage = stage + 2; if (nstage >= NSTAGES) nstage -= NSTAGES;
        if (cn < NCHUNK) issue(cn, nstage);
        cp_commit();

        const float* As = sm + OF_PIPE + stage * STAGE_F;
        const uint32_t sb = pipe_sm + (uint32_t)stage * STAGE_BYTES;

        #pragma unroll
        for (int ksi = 0; ksi < 2; ++ksi) {
            const int ks = (ksi * 16 + kphase) & 31;   // even warps: 0,16; odd: 16,0
            // A fragments: fp32 LDS.64 + cvt
            uint32_t a[2][4];
            #pragma unroll
            for (int mi = 0; mi < 2; ++mi) {
                const float2* r0 = (const float2*)(As + (mw + mi * 16 + tg) * APITCH + ks);
                const float2* r1 = (const float2*)(As + (mw + mi * 16 + tg + 8) * APITCH + ks);
                float2 v0 = r0[tk], v1 = r1[tk], v2 = r0[tk + 4], v3 = r1[tk + 4];
                a[mi][0] = pack_f16x2(v0.x, v0.y);
                a[mi][1] = pack_f16x2(v1.x, v1.y);
                a[mi][2] = pack_f16x2(v2.x, v2.y);
                a[mi][3] = pack_f16x2(v3.x, v3.y);
            }
            // B fragments: ldmatrix.x4
            uint32_t b[8][2];
            #pragma unroll
            for (int g = 0; g < 4; ++g) {
                uint32_t r[4];
                ldmatrix_x4(r, sb + b_lm + (uint32_t)(g * 16 * 80 + ks * 2));
                b[2 * g][0]     = r[0]; b[2 * g][1]     = r[1];
                b[2 * g + 1][0] = r[2]; b[2 * g + 1][1] = r[3];
            }
            #pragma unroll
            for (int mi = 0; mi < 2; ++mi)
                #pragma unroll
                for (int ni = 0; ni < 8; ++ni)
                    mma_f16(acc[mi][ni], a[mi], b[ni][0], b[ni][1]);
        }
        ++stage; if (stage >= NSTAGES) stage = 0;
    }

    // ---- epilogue: h = relu(acc + b1) into smem overlay (R10-verbatim) ----
    cp_wait0();
    __syncthreads();
    {
        float* h = sm + OF_PIPE;   // [128][PH]
        #pragma unroll
        for (int mi = 0; mi < 2; ++mi) {
            #pragma unroll
            for (int ni = 0; ni < 8; ++ni) {
                const int r = mw + mi * 16 + tg;
                const int n = nw + ni * 8 + 2 * tk;
                const float bn0 = sm[OF_B1 + n], bn1 = sm[OF_B1 + n + 1];
                h[r * PH + n]           = fmaxf(acc[mi][ni][0] + bn0, 0.f);
                h[r * PH + n + 1]       = fmaxf(acc[mi][ni][1] + bn1, 0.f);
                h[(r + 8) * PH + n]     = fmaxf(acc[mi][ni][2] + bn0, 0.f);
                h[(r + 8) * PH + n + 1] = fmaxf(acc[mi][ni][3] + bn1, 0.f);
            }
        }
    }
    __syncthreads();

    // ---- GEMM2: split-K over 2 threads/row ----
    {
        const float* h = sm + OF_PIPE;
        const int row  = tid & 127;
        const int half = tid >> 7;
        float o[10];
        #pragma unroll
        for (int n = 0; n < 10; ++n) o[n] = 0.f;
        #pragma unroll 8
        for (int k = half * 64; k < half * 64 + 64; ++k) {
            const float t = h[row * PH + k];
            const float* wr = sm + OF_W2 + k * 10;
            #pragma unroll
            for (int n = 0; n < 10; ++n) o[n] = fmaf(t, wr[n], o[n]);
        }
        #pragma unroll
        for (int n = 0; n < 10; ++n) sm[OF_PART + tid * 10 + n] = o[n];
    }
    __syncthreads();
    if (tid < 128) {
        #pragma unroll
        for (int n = 0; n < 10; ++n)
            sm[OF_OUTS + tid * 10 + n] = sm[OF_PART + tid * 10 + n]
                                       + sm[OF_PART + (tid + 128) * 10 + n]
                                       + sm[OF_B2 + n];
    }
    __syncthreads();

    // ---- coalesced store ----
    const int nvalid = (Brows - m0 < MT) ? (Brows - m0) : MT;
    if (nvalid == MT) {
        float4* dst = (float4*)(out + (size_t)m0 * 10);
        const float4* src = (const float4*)(sm + OF_OUTS);
        for (int i = tid; i < MT * 10 / 4; i += THREADS) dst[i] = src[i];
    } else {
        for (int i = tid; i < nvalid * 10; i += THREADS) out[(size_t)m0 * 10 + i] = sm[OF_OUTS + i];
    }
}

// ============================================================================
// Host launch
// ============================================================================
extern "C" void kernel_launch(void* const* d_in, const int* in_sizes, int n_in,
                              void* d_out, int out_size) {
    const float* x      = (const float*)d_in[0];
    const float* conv_w = (const float*)d_in[1];
    const float* w1     = (const float*)d_in[2];
    const float* b1     = (const float*)d_in[3];
    const float* w2     = (const float*)d_in[4];
    const float* b2     = (const float*)d_in[5];
    float* out          = (float*)d_out;
    const int Brows     = in_sizes[0] / KDIM;

    static int configured = 0;
    if (!configured) {
        cudaFuncSetAttribute(fused_mlp_kernel, cudaFuncAttributeMaxDynamicSharedMemorySize, SMEM_BYTES);
        configured = 1;
    }

    prep_kernel<<<(NT * KPAD + 255) / 256, 256>>>(conv_w, w1);

    const int grid = (Brows + MT - 1) / MT;
    fused_mlp_kernel<<<grid, THREADS, SMEM_BYTES>>>(x, b1, w2, b2, out, Brows);
}